// round 16
// baseline (speedup 1.0000x reference)
#include <cuda_runtime.h>
#include <cuda_bf16.h>
#include <cstdint>

// Problem constants
#define T_TOK 4096
#define D_MODEL 2048
#define F_FF 8192
#define E_EXP 8

// GEMM tiling: 128x256 CTA tile, BK=32, 8 warps (2Mx4N), warp tile 64x64
#define BM 128
#define BN 256
#define BK 32
#define NTH 256
#define LDA_S 36                 // A smem stride (floats): bank=(4r+c)%32, conflict-free
#define LDB_S 264                // B smem stride (floats): 264%32=8, bank=(8k+n)%32, conflict-free
#define ABUF (BM * LDA_S)        // 4608 floats
#define BBUF (BK * LDB_S)        // 8448 floats
#define BUF_FLOATS (ABUF + BBUF) // 13056
#define SMEM_BYTES (2 * BUF_FLOATS * 4)   // 104448 B

// ---------------------------------------------------------------------------
// Device scratch
// ---------------------------------------------------------------------------
__device__ int   g_idx[T_TOK];
__device__ float g_w[T_TOK];
__device__ int   g_cnt[E_EXP];
__device__ int   g_off[E_EXP + 1];
__device__ int   g_slot[T_TOK];
__device__ int   g_perm[T_TOK];
__device__ float g_H[(size_t)T_TOK * F_FF];   // 128 MB fp32 hidden scratch

// ---------------------------------------------------------------------------
// PTX helpers
// ---------------------------------------------------------------------------
__device__ __forceinline__ void cp_async16(uint32_t dst, const void* src) {
    asm volatile("cp.async.cg.shared.global [%0], [%1], 16;\n" :: "r"(dst), "l"(src));
}
__device__ __forceinline__ void cp_commit() {
    asm volatile("cp.async.commit_group;\n");
}
template <int N>
__device__ __forceinline__ void cp_wait() {
    asm volatile("cp.async.wait_group %0;\n" :: "n"(N));
}
__device__ __forceinline__ uint32_t f2tf32(float f) {
    uint32_t r;
    asm("cvt.rna.tf32.f32 %0, %1;" : "=r"(r) : "f"(f));
    return r;
}
__device__ __forceinline__ void mma_tf32(float* c, const uint32_t* a, const uint32_t* b) {
    asm volatile(
        "mma.sync.aligned.m16n8k8.row.col.f32.tf32.tf32.f32 "
        "{%0,%1,%2,%3}, {%4,%5,%6,%7}, {%8,%9}, {%0,%1,%2,%3};"
        : "+f"(c[0]), "+f"(c[1]), "+f"(c[2]), "+f"(c[3])
        : "r"(a[0]), "r"(a[1]), "r"(a[2]), "r"(a[3]), "r"(b[0]), "r"(b[1]));
}

// ---------------------------------------------------------------------------
// Kernel 0-3: routing pipeline (unchanged, known-good)
// ---------------------------------------------------------------------------
__global__ void init_kernel() {
    if (threadIdx.x < E_EXP) g_cnt[threadIdx.x] = 0;
}

__global__ void router_kernel(const float* __restrict__ x,
                              const float* __restrict__ Wr) {
    const int t   = blockIdx.x;
    const int tid = threadIdx.x;
    __shared__ float red[E_EXP][128];

    const float* xr = x + (size_t)t * D_MODEL;
    float acc[E_EXP];
#pragma unroll
    for (int e = 0; e < E_EXP; e++) acc[e] = 0.f;

    for (int d = tid; d < D_MODEL; d += 128) {
        float xv = xr[d];
#pragma unroll
        for (int e = 0; e < E_EXP; e++)
            acc[e] = fmaf(xv, Wr[(size_t)e * D_MODEL + d], acc[e]);
    }
#pragma unroll
    for (int e = 0; e < E_EXP; e++) red[e][tid] = acc[e];
    __syncthreads();

    for (int s = 64; s > 0; s >>= 1) {
        if (tid < s) {
#pragma unroll
            for (int e = 0; e < E_EXP; e++) red[e][tid] += red[e][tid + s];
        }
        __syncthreads();
    }

    if (tid == 0) {
        float m = red[0][0];
        int   bi = 0;
#pragma unroll
        for (int e = 1; e < E_EXP; e++) {
            float v = red[e][0];
            if (v > m) { m = v; bi = e; }   // strict > keeps first max (jnp.argmax)
        }
        float s = 0.f;
#pragma unroll
        for (int e = 0; e < E_EXP; e++) s += expf(red[e][0] - m);
        g_idx[t]  = bi;
        g_w[t]    = 1.0f / s;
        g_slot[t] = atomicAdd(&g_cnt[bi], 1);
    }
}

__global__ void offsets_kernel() {
    if (threadIdx.x == 0) {
        int s = 0;
        for (int e = 0; e < E_EXP; e++) { g_off[e] = s; s += g_cnt[e]; }
        g_off[E_EXP] = s;
    }
}

__global__ void perm_kernel() {
    int t = blockIdx.x * 256 + threadIdx.x;
    if (t < T_TOK) g_perm[g_off[g_idx[t]] + g_slot[t]] = t;
}

__device__ __forceinline__ float gelu_exact(float v) {
    return 0.5f * v * (1.0f + erff(v * 0.70710678118654752440f));
}

// ---------------------------------------------------------------------------
// Core mma.sync tf32 mainloop (shared by both GEMMs).
// Warp layout: warpM = warp&1 (64 rows), warpN = warp>>1 (64 cols).
// Per warp: 4 M-tiles (m16) x 8 N-tiles (n8), k-steps of 8.
// ---------------------------------------------------------------------------
struct Frag { float acc[4][8][4]; };

__device__ __forceinline__ void mma_tile_step(Frag& F, const float* As, const float* Bs,
                                              int warpM, int warpN, int lane) {
#pragma unroll
    for (int ks = 0; ks < BK / 8; ks++) {
        const float* Awp = As + (warpM * 64 + (lane >> 2)) * LDA_S + ks * 8 + (lane & 3);
        uint32_t ar[4][4];
#pragma unroll
        for (int mt = 0; mt < 4; mt++) {
            const float* ab = Awp + mt * 16 * LDA_S;
            ar[mt][0] = f2tf32(ab[0]);
            ar[mt][1] = f2tf32(ab[8 * LDA_S]);
            ar[mt][2] = f2tf32(ab[4]);
            ar[mt][3] = f2tf32(ab[8 * LDA_S + 4]);
        }
        const float* Bwp = Bs + (ks * 8 + (lane & 3)) * LDB_S + warpN * 64 + (lane >> 2);
        uint32_t br[8][2];
#pragma unroll
        for (int nt = 0; nt < 8; nt++) {
            br[nt][0] = f2tf32(Bwp[nt * 8]);
            br[nt][1] = f2tf32(Bwp[4 * LDB_S + nt * 8]);
        }
#pragma unroll
        for (int mt = 0; mt < 4; mt++)
#pragma unroll
            for (int nt = 0; nt < 8; nt++)
                mma_tf32(F.acc[mt][nt], ar[mt], br[nt]);
    }
}

// ---------------------------------------------------------------------------
// GEMM1: H[off+m, f] = gelu( sum_k X[perm[off+m], k] * W1[e][k][f] )
// ---------------------------------------------------------------------------
__global__ __launch_bounds__(NTH)
void gemm1_kernel(const float* __restrict__ x, const float* __restrict__ W1) {
    const int e = blockIdx.z, mt_blk = blockIdx.y, nt_blk = blockIdx.x;
    const int cnt = g_cnt[e], off = g_off[e];
    if (mt_blk * BM >= cnt) return;

    extern __shared__ float smem[];
    const int tid  = threadIdx.x;
    const int warp = tid >> 5, lane = tid & 31;
    const int warpM = warp & 1, warpN = warp >> 1;

    // A gather: 128 rows x 32 floats; 256 threads -> 4 float4 each (16 floats).
    const int rA = tid >> 1;            // 0..127
    const int cA = (tid & 1) * 16;      // 0 or 16
    int growA = mt_blk * BM + rA;
    int rcA = growA < cnt ? growA : cnt - 1;
    const float* aSrc = x + (size_t)g_perm[off + rcA] * D_MODEL + cA;
    // B: 32 k-rows x 256 floats; 256 threads -> 8 float4 each (32 floats).
    const int rB = tid >> 3;            // 0..31
    const int cB = (tid & 7) * 32;      // 0..224
    const float* bSrc = W1 + (size_t)e * D_MODEL * F_FF
                           + (size_t)rB * F_FF + (size_t)nt_blk * BN + cB;

    uint32_t dA = (uint32_t)__cvta_generic_to_shared(&smem[rA * LDA_S + cA]);
    uint32_t dB = (uint32_t)__cvta_generic_to_shared(&smem[ABUF + rB * LDB_S + cB]);

    auto prefetch = [&](int b, int k0) {
        uint32_t add = (uint32_t)b * (uint32_t)(BUF_FLOATS * 4);
#pragma unroll
        for (int j = 0; j < 4; j++) cp_async16(dA + add + j * 16, aSrc + k0 + j * 4);
#pragma unroll
        for (int j = 0; j < 8; j++) cp_async16(dB + add + j * 16, bSrc + (size_t)k0 * F_FF + j * 4);
    };

    Frag F;
#pragma unroll
    for (int mt = 0; mt < 4; mt++)
#pragma unroll
        for (int nt = 0; nt < 8; nt++)
#pragma unroll
            for (int q = 0; q < 4; q++) F.acc[mt][nt][q] = 0.f;

    const int NKT = D_MODEL / BK;   // 64
    prefetch(0, 0);
    cp_commit();

#pragma unroll 1
    for (int kt = 0; kt < NKT; kt++) {
        const int cur = kt & 1;
        if (kt + 1 < NKT) {
            prefetch(cur ^ 1, (kt + 1) * BK);
            cp_commit();
            cp_wait<1>();
        } else {
            cp_wait<0>();
        }
        __syncthreads();
        const float* As = smem + cur * BUF_FLOATS;
        mma_tile_step(F, As, As + ABUF, warpM, warpN, lane);
        __syncthreads();
    }

    // Epilogue: GELU, direct float2 stores to compact H
    const int rbase = mt_blk * BM + warpM * 64 + (lane >> 2);
    const int cbase = nt_blk * BN + warpN * 64 + (lane & 3) * 2;
#pragma unroll
    for (int mt = 0; mt < 4; mt++) {
        int r0 = rbase + mt * 16;
#pragma unroll
        for (int h = 0; h < 2; h++) {
            int gr = r0 + h * 8;
            if (gr < cnt) {
                float* hb = g_H + (size_t)(off + gr) * F_FF;
#pragma unroll
                for (int nt = 0; nt < 8; nt++) {
                    float2 v;
                    v.x = gelu_exact(F.acc[mt][nt][h * 2 + 0]);
                    v.y = gelu_exact(F.acc[mt][nt][h * 2 + 1]);
                    *(float2*)(hb + cbase + nt * 8) = v;
                }
            }
        }
    }
}

// ---------------------------------------------------------------------------
// GEMM2: out[tok, d] = w[tok] * sum_f H[off+m, f] * W2[e][f][d]
// ---------------------------------------------------------------------------
__global__ __launch_bounds__(NTH)
void gemm2_kernel(const float* __restrict__ W2, float* __restrict__ out) {
    const int e = blockIdx.z, mt_blk = blockIdx.y, nt_blk = blockIdx.x;
    const int cnt = g_cnt[e], off = g_off[e];
    if (mt_blk * BM >= cnt) return;

    extern __shared__ float smem[];
    const int tid  = threadIdx.x;
    const int warp = tid >> 5, lane = tid & 31;
    const int warpM = warp & 1, warpN = warp >> 1;

    const int rA = tid >> 1;
    const int cA = (tid & 1) * 16;
    int growA = mt_blk * BM + rA;
    int rcA = growA < cnt ? growA : cnt - 1;
    const float* aSrc = g_H + (size_t)(off + rcA) * F_FF + cA;
    const int rB = tid >> 3;
    const int cB = (tid & 7) * 32;
    const float* bSrc = W2 + (size_t)e * F_FF * D_MODEL
                           + (size_t)rB * D_MODEL + (size_t)nt_blk * BN + cB;

    uint32_t dA = (uint32_t)__cvta_generic_to_shared(&smem[rA * LDA_S + cA]);
    uint32_t dB = (uint32_t)__cvta_generic_to_shared(&smem[ABUF + rB * LDB_S + cB]);

    auto prefetch = [&](int b, int k0) {
        uint32_t add = (uint32_t)b * (uint32_t)(BUF_FLOATS * 4);
#pragma unroll
        for (int j = 0; j < 4; j++) cp_async16(dA + add + j * 16, aSrc + k0 + j * 4);
#pragma unroll
        for (int j = 0; j < 8; j++) cp_async16(dB + add + j * 16, bSrc + (size_t)k0 * D_MODEL + j * 4);
    };

    Frag F;
#pragma unroll
    for (int mt = 0; mt < 4; mt++)
#pragma unroll
        for (int nt = 0; nt < 8; nt++)
#pragma unroll
            for (int q = 0; q < 4; q++) F.acc[mt][nt][q] = 0.f;

    const int NKT = F_FF / BK;   // 256
    prefetch(0, 0);
    cp_commit();

#pragma unroll 1
    for (int kt = 0; kt < NKT; kt++) {
        const int cur = kt & 1;
        if (kt + 1 < NKT) {
            prefetch(cur ^ 1, (kt + 1) * BK);
            cp_commit();
            cp_wait<1>();
        } else {
            cp_wait<0>();
        }
        __syncthreads();
        const float* As = smem + cur * BUF_FLOATS;
        mma_tile_step(F, As, As + ABUF, warpM, warpN, lane);
        __syncthreads();
    }

    // Epilogue: scale by router weight, scatter float2 to out[token]
    const int rbase = mt_blk * BM + warpM * 64 + (lane >> 2);
    const int cbase = nt_blk * BN + warpN * 64 + (lane & 3) * 2;
#pragma unroll
    for (int mt = 0; mt < 4; mt++) {
        int r0 = rbase + mt * 16;
#pragma unroll
        for (int h = 0; h < 2; h++) {
            int gr = r0 + h * 8;
            if (gr < cnt) {
                int tok = g_perm[off + gr];
                float wgt = g_w[tok];
                float* ob = out + (size_t)tok * D_MODEL;
#pragma unroll
                for (int nt = 0; nt < 8; nt++) {
                    float2 v;
                    v.x = F.acc[mt][nt][h * 2 + 0] * wgt;
                    v.y = F.acc[mt][nt][h * 2 + 1] * wgt;
                    *(float2*)(ob + cbase + nt * 8) = v;
                }
            }
        }
    }
}

// ---------------------------------------------------------------------------
// Launch
// ---------------------------------------------------------------------------
extern "C" void kernel_launch(void* const* d_in, const int* in_sizes, int n_in,
                              void* d_out, int out_size) {
    const float* x  = (const float*)d_in[0];   // [T, D]
    const float* Wr = (const float*)d_in[1];   // [E, D]
    const float* W1 = (const float*)d_in[2];   // [E, D, F]
    const float* W2 = (const float*)d_in[3];   // [E, F, D]
    float* out = (float*)d_out;                // [T, D]

    cudaFuncSetAttribute(gemm1_kernel,
                         cudaFuncAttributeMaxDynamicSharedMemorySize, SMEM_BYTES);
    cudaFuncSetAttribute(gemm2_kernel,
                         cudaFuncAttributeMaxDynamicSharedMemorySize, SMEM_BYTES);

    init_kernel<<<1, 32>>>();
    router_kernel<<<T_TOK, 128>>>(x, Wr);
    offsets_kernel<<<1, 32>>>();
    perm_kernel<<<T_TOK / 256, 256>>>();

    dim3 g1(F_FF / BN, T_TOK / BM, E_EXP);     // (32, 32, 8)
    gemm1_kernel<<<g1, NTH, SMEM_BYTES>>>(x, W1);

    dim3 g2(D_MODEL / BN, T_TOK / BM, E_EXP);  // (8, 32, 8)
    gemm2_kernel<<<g2, NTH, SMEM_BYTES>>>(W2, out);
}